// round 3
// baseline (speedup 1.0000x reference)
#include <cuda_runtime.h>
#include <math.h>

// 2-layer LSTM, H=512, B=16, persistent kernel, grid-wide software barrier.
// 128 CTAs; CTA c owns h-indices [4c, 4c+4) => 16 gate rows per layer
// (rows j = g*512 + 4c + l for gate g in {i,f,g,o}, l in 0..3).
// Weights live in shared memory for the whole sequence.

#define NCTA  128
#define NTHR  256
#define HD    512
#define BQ    16
#define SP    516           // padded row stride (floats) for bank-conflict-free float4 loads
#define NROWS 16

__device__ __align__(16) float g_h1[BQ * HD];
__device__ __align__(16) float g_h2[BQ * HD];
__device__ unsigned g_bar_count = 0;
__device__ unsigned g_bar_gen   = 0;

__device__ __forceinline__ float sigmoidf_(float x) { return 1.0f / (1.0f + expf(-x)); }

__device__ __forceinline__ void grid_barrier() {
    __threadfence();
    __syncthreads();
    if (threadIdx.x == 0) {
        unsigned gen = *(volatile unsigned*)&g_bar_gen;
        if (atomicAdd(&g_bar_count, 1u) == NCTA - 1u) {
            atomicExch(&g_bar_count, 0u);
            __threadfence();
            atomicExch(&g_bar_gen, gen + 1u);
        } else {
            while (*(volatile unsigned*)&g_bar_gen == gen) { }
        }
    }
    __syncthreads();
    __threadfence();
}

__global__ void __launch_bounds__(NTHR, 1) lstm_kernel(
    const float* __restrict__ input,
    const float* __restrict__ Wih1, const float* __restrict__ Whh1,
    const float* __restrict__ bih1, const float* __restrict__ bhh1,
    const float* __restrict__ Wih2, const float* __restrict__ Whh2,
    const float* __restrict__ bih2, const float* __restrict__ bhh2,
    const float* __restrict__ Wout, const float* __restrict__ bout,
    float* __restrict__ out, int T)
{
    extern __shared__ float sm[];
    float* W1    = sm;                    // [16][SP]  Whh1 slice
    float* W2A   = W1  + NROWS * SP;      // [16][SP]  Wih2 slice
    float* W2B   = W2A + NROWS * SP;      // [16][SP]  Whh2 slice
    float* HB1   = W2B + NROWS * SP;      // [16][SP]  h1 (all batches)
    float* HB2   = HB1 + BQ * SP;         // [16][SP]  h2 (all batches)
    float* PART  = HB2 + BQ * SP;         // [2][16][17] partial gate sums
    float* BIAS1 = PART + 2 * 16 * 17;    // [16]
    float* BIAS2 = BIAS1 + 16;            // [16]
    float* WI1   = BIAS2 + 16;            // [16][2]
    float* C1S   = WI1 + 32;              // [4][16]
    float* C2S   = C1S + 64;              // [4][16]
    float* XS    = C2S + 64;              // [2][16]

    const int tid   = threadIdx.x;
    const int cta   = blockIdx.x;
    const int hbase = cta * 4;

    // ---- preamble: stage weights for our 16 rows (per layer) into smem ----
    for (int idx = tid; idx < NROWS * 128; idx += NTHR) {
        int r  = idx >> 7;
        int k4 = idx & 127;
        int g = r >> 2, l = r & 3;
        int j = g * HD + hbase + l;
        ((float4*)(W1  + r * SP))[k4] = ((const float4*)(Whh1 + (size_t)j * HD))[k4];
        ((float4*)(W2A + r * SP))[k4] = ((const float4*)(Wih2 + (size_t)j * HD))[k4];
        ((float4*)(W2B + r * SP))[k4] = ((const float4*)(Whh2 + (size_t)j * HD))[k4];
    }
    if (tid < 16) {
        int r = tid, g = r >> 2, l = r & 3;
        int j = g * HD + hbase + l;
        BIAS1[r] = bih1[j] + bhh1[j];
        BIAS2[r] = bih2[j] + bhh2[j];
        WI1[2 * r]     = Wih1[2 * j];
        WI1[2 * r + 1] = Wih1[2 * j + 1];
    }
    for (int idx = tid; idx < BQ * SP; idx += NTHR) { HB1[idx] = 0.0f; HB2[idx] = 0.0f; }
    if (tid < 64) { C1S[tid] = 0.0f; C2S[tid] = 0.0f; }
    const float bo = bout[0];
    __syncthreads();

    // warp work decomposition:
    //   khalf = warp>>2 selects K-half (layer1) / weight matrix (layer2)
    //   rg    = warp&3  selects a group of 4 rows
    //   lanes 0-15: batch=lane, rows (rg*4+0, rg*4+1)
    //   lanes16-31: batch=lane-16, rows (rg*4+2, rg*4+3)
    const int warp  = tid >> 5, lane = tid & 31;
    const int bq    = lane & 15;
    const int rp    = lane >> 4;
    const int rg    = warp & 3;
    const int khalf = warp >> 2;
    const int rowA  = rg * 4 + rp * 2;
    const int rowB  = rowA + 1;

    for (int t = 0; t < T; ++t) {
        // ---------------- Phase A: layer 1 ----------------
        if (tid < 32) {
            int b = tid & 15, c = tid >> 4;
            XS[c * 16 + b] = input[((size_t)b * T + t) * 2 + c];
        }
        __syncthreads();

        {   // gates1 partial: Whh1 slice @ h1_prev (K=512 split in two halves)
            const float4* wa = (const float4*)(W1 + rowA * SP + khalf * 256);
            const float4* wb = (const float4*)(W1 + rowB * SP + khalf * 256);
            const float4* uu = (const float4*)(HB1 + bq * SP + khalf * 256);
            float a0 = 0.0f, a1 = 0.0f;
            #pragma unroll 8
            for (int i = 0; i < 64; ++i) {
                float4 A = wa[i], Bv = wb[i], U = uu[i];
                a0 = fmaf(A.x,  U.x, a0); a0 = fmaf(A.y,  U.y, a0);
                a0 = fmaf(A.z,  U.z, a0); a0 = fmaf(A.w,  U.w, a0);
                a1 = fmaf(Bv.x, U.x, a1); a1 = fmaf(Bv.y, U.y, a1);
                a1 = fmaf(Bv.z, U.z, a1); a1 = fmaf(Bv.w, U.w, a1);
            }
            PART[khalf * 272 + rowA * 17 + bq] = a0;
            PART[khalf * 272 + rowB * 17 + bq] = a1;
        }
        __syncthreads();

        if (tid < 64) {  // update c1, h1 for our 4 h-indices x 16 batches
            int l = tid >> 4, b = tid & 15;
            float x0 = XS[b], x1 = XS[16 + b];
            float gi = PART[(l     ) * 17 + b] + PART[272 + (l     ) * 17 + b]
                     + BIAS1[l]      + WI1[2 * (l)          ] * x0 + WI1[2 * (l)           + 1] * x1;
            float gf = PART[(4 + l ) * 17 + b] + PART[272 + (4 + l ) * 17 + b]
                     + BIAS1[4 + l]  + WI1[2 * (4 + l)      ] * x0 + WI1[2 * (4 + l)       + 1] * x1;
            float gg = PART[(8 + l ) * 17 + b] + PART[272 + (8 + l ) * 17 + b]
                     + BIAS1[8 + l]  + WI1[2 * (8 + l)      ] * x0 + WI1[2 * (8 + l)       + 1] * x1;
            float go = PART[(12 + l) * 17 + b] + PART[272 + (12 + l) * 17 + b]
                     + BIAS1[12 + l] + WI1[2 * (12 + l)     ] * x0 + WI1[2 * (12 + l)      + 1] * x1;
            float iv = sigmoidf_(gi);
            float fv = sigmoidf_(gf);
            float gv = tanhf(gg);
            float ov = sigmoidf_(go);
            float c  = fv * C1S[l * 16 + b] + iv * gv;
            C1S[l * 16 + b] = c;
            float h = ov * tanhf(c);
            g_h1[b * HD + hbase + l] = h;
        }
        grid_barrier();

        // ---------------- Phase B: layer 2 ----------------
        // reload full h1(t) into smem
        for (int idx = tid; idx < BQ * 128; idx += NTHR) {
            int b = idx >> 7, k4 = idx & 127;
            ((float4*)(HB1 + b * SP))[k4] = ((const float4*)(g_h1 + b * HD))[k4];
        }
        __syncthreads();

        {   // gates2 partial: warps 0-3: Wih2 @ h1(t); warps 4-7: Whh2 @ h2(t-1)
            const float* Wsrc = khalf ? W2B : W2A;
            const float* Usrc = khalf ? HB2 : HB1;
            const float4* wa = (const float4*)(Wsrc + rowA * SP);
            const float4* wb = (const float4*)(Wsrc + rowB * SP);
            const float4* uu = (const float4*)(Usrc + bq * SP);
            float a0 = 0.0f, a1 = 0.0f;
            #pragma unroll 8
            for (int i = 0; i < 128; ++i) {
                float4 A = wa[i], Bv = wb[i], U = uu[i];
                a0 = fmaf(A.x,  U.x, a0); a0 = fmaf(A.y,  U.y, a0);
                a0 = fmaf(A.z,  U.z, a0); a0 = fmaf(A.w,  U.w, a0);
                a1 = fmaf(Bv.x, U.x, a1); a1 = fmaf(Bv.y, U.y, a1);
                a1 = fmaf(Bv.z, U.z, a1); a1 = fmaf(Bv.w, U.w, a1);
            }
            PART[khalf * 272 + rowA * 17 + bq] = a0;
            PART[khalf * 272 + rowB * 17 + bq] = a1;
        }
        __syncthreads();

        if (tid < 64) {  // update c2, h2
            int l = tid >> 4, b = tid & 15;
            float gi = PART[(l     ) * 17 + b] + PART[272 + (l     ) * 17 + b] + BIAS2[l];
            float gf = PART[(4 + l ) * 17 + b] + PART[272 + (4 + l ) * 17 + b] + BIAS2[4 + l];
            float gg = PART[(8 + l ) * 17 + b] + PART[272 + (8 + l ) * 17 + b] + BIAS2[8 + l];
            float go = PART[(12 + l) * 17 + b] + PART[272 + (12 + l) * 17 + b] + BIAS2[12 + l];
            float iv = sigmoidf_(gi);
            float fv = sigmoidf_(gf);
            float gv = tanhf(gg);
            float ov = sigmoidf_(go);
            float c  = fv * C2S[l * 16 + b] + iv * gv;
            C2S[l * 16 + b] = c;
            float h = ov * tanhf(c);
            g_h2[b * HD + hbase + l] = h;
        }
        grid_barrier();

        // output head: CTA b (b<16), warp 0 computes out[b][t] = h2[b] . Wout + bout
        if (cta < BQ && warp == 0) {
            float s = 0.0f;
            const float* h2p = g_h2 + cta * HD;
            for (int k = lane; k < HD; k += 32) s += h2p[k] * Wout[k];
            #pragma unroll
            for (int o = 16; o; o >>= 1) s += __shfl_xor_sync(0xffffffffu, s, o);
            if (lane == 0) out[(size_t)cta * T + t] = s + bo;
        }
        // reload h2(t) into smem for next step's phase B
        for (int idx = tid; idx < BQ * 128; idx += NTHR) {
            int b = idx >> 7, k4 = idx & 127;
            ((float4*)(HB2 + b * SP))[k4] = ((const float4*)(g_h2 + b * HD))[k4];
        }
        __syncthreads();
    }
}

extern "C" void kernel_launch(void* const* d_in, const int* in_sizes, int n_in,
                              void* d_out, int out_size)
{
    const float* input = (const float*)d_in[0];
    const float* Wih1  = (const float*)d_in[1];
    const float* Whh1  = (const float*)d_in[2];
    const float* bih1  = (const float*)d_in[3];
    const float* bhh1  = (const float*)d_in[4];
    const float* Wih2  = (const float*)d_in[5];
    const float* Whh2  = (const float*)d_in[6];
    const float* bih2  = (const float*)d_in[7];
    const float* bhh2  = (const float*)d_in[8];
    const float* Wout  = (const float*)d_in[9];
    const float* bout  = (const float*)d_in[10];

    int T = in_sizes[0] / (BQ * 2);

    size_t smem_floats = 3 * NROWS * SP   // W1, W2A, W2B
                       + 2 * BQ * SP      // HB1, HB2
                       + 2 * 16 * 17      // PART
                       + 16 + 16 + 32     // BIAS1, BIAS2, WI1
                       + 64 + 64 + 32;    // C1S, C2S, XS
    size_t smem_bytes = smem_floats * sizeof(float);

    cudaFuncSetAttribute(lstm_kernel, cudaFuncAttributeMaxDynamicSharedMemorySize,
                         (int)smem_bytes);

    lstm_kernel<<<NCTA, NTHR, smem_bytes>>>(
        input, Wih1, Whh1, bih1, bhh1, Wih2, Whh2, bih2, bhh2, Wout, bout,
        (float*)d_out, T);
}